// round 8
// baseline (speedup 1.0000x reference)
#include <cuda_runtime.h>
#include <math.h>

#define NB    8
#define NPTS  4096
#define INF_F __int_as_float(0x7f800000)

// ---- scratch (device globals; no allocations allowed) ----
__device__ float  g_scal[8];                 // S1,1/S1,blend,Q1,cos(d1),sin(d1),d1
__device__ float  g_lstd[NB * NPTS * 3];
__device__ float  g_curv[NB * NPTS];
__device__ unsigned long long g_curvsum[NB]; // fixed-point (2^40) curvature sums
__device__ float4 g_sorted[NB * NPTS];       // per batch: points sorted by x; .w = orig idx bits

// ============================================================
// Kernel 1: fused per-(b,d) std + global consts + zero curvsum
// 1 block, 768 threads (24 warps, one per (b,d) column)
// ============================================================
__global__ void pre_kernel(const float* __restrict__ xyz) {
    __shared__ float sstd[24];
    int w = threadIdx.x >> 5, lane = threadIdx.x & 31;
    if (w < 24) {
        int b = w / 3, d = w % 3;
        const float* p = xyz + (size_t)b * NPTS * 3 + d;
        double s = 0.0, s2 = 0.0;
        for (int i = lane; i < NPTS; i += 32) {
            double v = (double)p[3 * i];
            s += v; s2 += v * v;
        }
        for (int o = 16; o; o >>= 1) {
            s  += __shfl_down_sync(0xffffffffu, s,  o);
            s2 += __shfl_down_sync(0xffffffffu, s2, o);
        }
        if (lane == 0) {
            double mean = s / NPTS;
            double var  = (s2 - (double)NPTS * mean * mean) / (NPTS - 1);
            sstd[w] = (float)sqrt(var > 0.0 ? var : 0.0);
        }
    }
    __syncthreads();
    if (threadIdx.x == 0) {
        double g = 0.0;
        for (int i = 0; i < 24; i++) g += (double)sstd[i];
        g /= 24.0;
        double asig  = 0.3 * (1.0 + g);
        double S1    = asig + 1e-6;
        double blend = 1.0 / (1.0 + exp(-(g - 0.1) * 10.0));
        double h  = 1.0 / 22.0;
        double d1 = h / S1;
        g_scal[0] = (float)S1;
        g_scal[1] = (float)(1.0 / S1);
        g_scal[2] = (float)blend;
        g_scal[3] = (float)exp(-d1 * d1);
        g_scal[4] = (float)cos(d1);
        g_scal[5] = (float)sin(d1);
        g_scal[6] = (float)d1;
        for (int b = 0; b < NB; b++) g_curvsum[b] = 0ull;
    }
}

// ============================================================
// Kernel 2: per-batch bitonic sort by x (u64 = flip(x)<<32 | idx),
// then build sorted float4 array (x,y,z, idx-bits). 8 blocks x 1024.
// ============================================================
__global__ void __launch_bounds__(1024)
sort_kernel(const float* __restrict__ xyz) {
    __shared__ unsigned long long keys[NPTS];
    int b = blockIdx.x, tid = threadIdx.x;
    const float* base = xyz + (size_t)b * NPTS * 3;

    for (int e = tid; e < NPTS; e += 1024) {
        unsigned u = __float_as_uint(base[3 * e]);
        u ^= (u & 0x80000000u) ? 0xFFFFFFFFu : 0x80000000u;   // total order flip
        keys[e] = ((unsigned long long)u << 32) | (unsigned)e;
    }
    __syncthreads();

    for (int k = 2; k <= NPTS; k <<= 1) {
        for (int j = k >> 1; j > 0; j >>= 1) {
#pragma unroll
            for (int s = 0; s < 4; s++) {
                int e = tid + (s << 10);
                int p = e ^ j;
                if (p > e) {
                    unsigned long long a = keys[e], c = keys[p];
                    bool asc = ((e & k) == 0);
                    if ((a > c) == asc) { keys[e] = c; keys[p] = a; }
                }
            }
            __syncthreads();
        }
    }

    for (int e = tid; e < NPTS; e += 1024) {
        int idx = (int)(unsigned)(keys[e] & 0xFFFFFFFFu);
        float x = base[3 * idx], y = base[3 * idx + 1], z = base[3 * idx + 2];
        g_sorted[b * NPTS + e] = make_float4(x, y, z, __int_as_float(idx));
    }
}

// ============================================================
// Kernel 3: kNN via sorted-x window expansion, one thread per point.
// Top-17 kept as sorted u64 (d2bits<<32 | sortedPos). Fused cov/eigen.
// grid (32, NB), 128 threads, 64KB dyn smem
// ============================================================
__device__ __forceinline__ void insert17(unsigned long long* L, unsigned long long pk) {
#pragma unroll
    for (int t = 16; t > 0; t--) {
        bool lt  = pk < L[t];
        bool ltp = pk < L[t - 1];
        if (lt) L[t] = ltp ? L[t - 1] : pk;
    }
    if (pk < L[0]) L[0] = pk;
}

__global__ void __launch_bounds__(128, 3)
knn_kernel() {
    extern __shared__ float4 P[];   // 4096 * 16B = 64KB
    int b = blockIdx.y;
    for (int i = threadIdx.x; i < NPTS; i += 128) P[i] = g_sorted[b * NPTS + i];
    __syncthreads();

    int wi   = threadIdx.x >> 5, lane = threadIdx.x & 31;
    int wg   = wi * gridDim.x + blockIdx.x;     // strided warp->region map (balance)
    int sp   = wg * 32 + lane;                  // sorted position of own point
    float4 q = P[sp];

    unsigned long long L[17];
#pragma unroll
    for (int t = 0; t < 17; t++) L[t] = ~0ull;
    insert17(L, (unsigned long long)(unsigned)sp);   // self: d2 = exactly 0

    int lo = sp, hi = sp;
    float thr = __uint_as_float((unsigned)(L[16] >> 32));   // NaN until 17 filled

    while (true) {
        float dLo = (lo > 0)        ? (q.x - P[lo - 1].x) : INF_F;
        float dHi = (hi < NPTS - 1) ? (P[hi + 1].x - q.x) : INF_F;
        bool  goLo = dLo <= dHi;
        float dmin = goLo ? dLo : dHi;
        if (dmin * dmin > thr) break;    // NaN thr (list unfilled) -> keep scanning

#pragma unroll
        for (int u = 1; u <= 8; u++) {
            int  j     = goLo ? (lo - u) : (hi + u);
            bool valid = goLo ? (j >= 0) : (j < NPTS);
            int  jc    = j < 0 ? 0 : (j > NPTS - 1 ? NPTS - 1 : j);
            float4 c = P[jc];
            float dx = q.x - c.x, dy = q.y - c.y, dz = q.z - c.z;
            float d2 = fmaf(dz, dz, fmaf(dy, dy, dx * dx));
            unsigned long long pk = valid
                ? ((((unsigned long long)__float_as_uint(d2)) << 32) | (unsigned)j)
                : ~0ull;
            bool pass = pk < L[16];
            if (__any_sync(__activemask(), pass)) insert17(L, pk);
        }
        if (goLo) lo -= 8; else hi += 8;
        thr = __uint_as_float((unsigned)(L[16] >> 32));
    }

    // ---- neighbor stats: mean, then centered covariance (fp32), eigen (fp64) ----
    float mx = 0.f, my = 0.f, mz = 0.f;
#pragma unroll
    for (int t = 1; t < 17; t++) {
        float4 nb = P[(unsigned)L[t] & 0xFFFFFFFFu];
        mx += nb.x; my += nb.y; mz += nb.z;
    }
    mx *= 0.0625f; my *= 0.0625f; mz *= 0.0625f;

    float cxxf = 0.f, cyyf = 0.f, czzf = 0.f, cxyf = 0.f, cxzf = 0.f, cyzf = 0.f;
#pragma unroll
    for (int t = 1; t < 17; t++) {
        float4 nb = P[(unsigned)L[t] & 0xFFFFFFFFu];
        float ax = nb.x - mx, ay = nb.y - my, az = nb.z - mz;
        cxxf = fmaf(ax, ax, cxxf); cyyf = fmaf(ay, ay, cyyf); czzf = fmaf(az, az, czzf);
        cxyf = fmaf(ax, ay, cxyf); cxzf = fmaf(ax, az, cxzf); cyzf = fmaf(ay, az, cyzf);
    }

    double cxx = (double)cxxf / 15.0, cyy = (double)cyyf / 15.0, czz = (double)czzf / 15.0;
    double cxy = (double)cxyf / 15.0, cxz = (double)cxzf / 15.0, cyz = (double)cyzf / 15.0;

    double tr = cxx + cyy + czz;
    double qm = tr / 3.0;
    double aa = cxx - qm, bb = cyy - qm, cc2 = czz - qm;
    double p2 = aa * aa + bb * bb + cc2 * cc2
              + 2.0 * (cxy * cxy + cxz * cxz + cyz * cyz);
    double lmin;
    if (p2 <= 1e-300) {
        lmin = qm;
    } else {
        double pp  = sqrt(p2 / 6.0);
        double inv = 1.0 / pp;
        double b00 = aa * inv, b11 = bb * inv, b22 = cc2 * inv;
        double b01 = cxy * inv, b02 = cxz * inv, b12 = cyz * inv;
        double det = b00 * (b11 * b22 - b12 * b12)
                   - b01 * (b01 * b22 - b12 * b02)
                   + b02 * (b01 * b12 - b11 * b02);
        double r = 0.5 * det;
        r = r < -1.0 ? -1.0 : (r > 1.0 ? 1.0 : r);
        double phi = acos(r) * (1.0 / 3.0);
        lmin = qm + 2.0 * pp * cos(phi + 2.0943951023931953);
    }

    double curv = lmin / (tr + 1e-6);
    int orig = __float_as_int(q.w);
    int gi   = b * NPTS + orig;
    g_curv[gi] = (float)curv;
    g_lstd[gi * 3 + 0] = (float)sqrt(cxx > 0.0 ? cxx : 0.0);
    g_lstd[gi * 3 + 1] = (float)sqrt(cyy > 0.0 ? cyy : 0.0);
    g_lstd[gi * 3 + 2] = (float)sqrt(czz > 0.0 ? czz : 0.0);

    long long sc = llrint(curv * 1099511627776.0);   // 2^40 fixed point (deterministic)
    atomicAdd(&g_curvsum[b], (unsigned long long)sc);
}

// ============================================================
// Kernel 4: embedding via geometric/rotation recurrences
// block = 96 threads (32 points x 3 dims), grid (NPTS/32, NB)
// ============================================================
__global__ void __launch_bounds__(96)
embed_kernel(const float* __restrict__ xyz, float* __restrict__ out) {
    __shared__ float sm[32][129];
    int tid = threadIdx.x;
    int p = tid & 31;
    int d = tid >> 5;
    int b = blockIdx.y;
    int n0 = blockIdx.x * 32;
    int gp = b * NPTS + n0 + p;

    float x    = xyz[(size_t)gp * 3 + d];
    float lstd = g_lstd[(size_t)gp * 3 + d];
    float curv = g_curv[gp];
    float cm   = (float)((double)(long long)g_curvsum[b]
                         * (1.0 / 1099511627776.0) * (1.0 / 4096.0));
    float w    = 1.0f / (1.0f + __expf(-10.0f * (curv - cm)));

    float invS1 = g_scal[1], blend = g_scal[2];
    float Q1 = g_scal[3], cd1 = g_scal[4], sd1 = g_scal[5], d1 = g_scal[6];

    float Aw = w * blend;
    float Bw = w * (1.0f - blend);
    float Cw = 1.0f - w;

    const float h   = 0.045454545454545456f;   // 1/22
    const float fv0 = -0.9545454545454546f;    // FEAT_VAL[0]

    float S2   = fmaf(0.3f, lstd, 0.3f) + 1e-6f;
    float inv2 = 1.0f / S2;
    float d2s  = h * inv2;
    float Q2   = __expf(-d2s * d2s);

    bool  up  = (x <= 0.0f);
    float sgn = up ? 1.0f : -1.0f;
    int   f   = up ? 0 : 42;
    int   df  = up ? 1 : -1;
    float fva = up ? fv0 : -fv0;

    float t1 = (x - fva) * invS1;
    float t2 = (x - fva) * inv2;
    float G1 = __expf(-0.5f * t1 * t1);
    float G2 = __expf(-0.5f * t2 * t2);
    float r1 = __expf(sgn * d1  * (t1 - sgn * 0.5f * d1));
    float r2 = __expf(sgn * d2s * (t2 - sgn * 0.5f * d2s));
    float cc = __cosf(t1);
    float sn = __sinf(t1);
    float sd = up ? sd1 : -sd1;

    for (int it = 0; it < 43; it++) {
        float val = fmaf(Aw, G1, fmaf(Bw, cc, Cw * G2));
        int col;
        if (d < 2) col = d * 43 + f;
        else       col = (f < 41) ? (86 + f) : ((f == 42) ? 127 : -1);
        if (col >= 0) sm[p][col] = val;
        G1 *= r1; r1 *= Q1;
        G2 *= r2; r2 *= Q2;
        float cn  = fmaf(cc, cd1,  sn * sd);
        float sn2 = fmaf(sn, cd1, -cc * sd);
        cc = cn; sn = sn2;
        f += df;
    }
    __syncthreads();

    float* ob = out + ((size_t)b * NPTS + n0) * 128;
    for (int i = tid; i < 32 * 128; i += 96)
        ob[i] = sm[i >> 7][i & 127];
}

// ============================================================
extern "C" void kernel_launch(void* const* d_in, const int* in_sizes, int n_in,
                              void* d_out, int out_size) {
    const float* xyz = (const float*)d_in[0];
    float* out = (float*)d_out;
    (void)in_sizes; (void)n_in; (void)out_size;

    const int knn_smem = NPTS * 16;   // 65536 B
    cudaFuncSetAttribute(knn_kernel, cudaFuncAttributeMaxDynamicSharedMemorySize, knn_smem);

    pre_kernel<<<1, 768>>>(xyz);
    sort_kernel<<<NB, 1024>>>(xyz);
    dim3 kg(32, NB);
    knn_kernel<<<kg, 128, knn_smem>>>();
    dim3 eg(NPTS / 32, NB);
    embed_kernel<<<eg, 96>>>(xyz, out);
}

// round 9
// speedup vs baseline: 1.0954x; 1.0954x over previous
#include <cuda_runtime.h>
#include <math.h>

#define NB    8
#define NPTS  4096
#define INF_F __int_as_float(0x7f800000)

// ---- scratch (device globals; no allocations allowed) ----
__device__ float  g_scal[8];                 // S1,1/S1,blend,Q1,cos(d1),sin(d1),d1
__device__ float  g_lstd[NB * NPTS * 3];
__device__ float  g_curv[NB * NPTS];
__device__ unsigned long long g_curvsum[NB]; // fixed-point (2^40) curvature sums
__device__ float4 g_sorted[NB * NPTS];       // per batch: sorted by x; .w = orig idx bits

// ============================================================
// Kernel 1: fused per-(b,d) std + global consts + zero curvsum
// ============================================================
__global__ void pre_kernel(const float* __restrict__ xyz) {
    __shared__ float sstd[24];
    int w = threadIdx.x >> 5, lane = threadIdx.x & 31;
    if (w < 24) {
        int b = w / 3, d = w % 3;
        const float* p = xyz + (size_t)b * NPTS * 3 + d;
        double s = 0.0, s2 = 0.0;
        for (int i = lane; i < NPTS; i += 32) {
            double v = (double)p[3 * i];
            s += v; s2 += v * v;
        }
        for (int o = 16; o; o >>= 1) {
            s  += __shfl_down_sync(0xffffffffu, s,  o);
            s2 += __shfl_down_sync(0xffffffffu, s2, o);
        }
        if (lane == 0) {
            double mean = s / NPTS;
            double var  = (s2 - (double)NPTS * mean * mean) / (NPTS - 1);
            sstd[w] = (float)sqrt(var > 0.0 ? var : 0.0);
        }
    }
    __syncthreads();
    if (threadIdx.x == 0) {
        double g = 0.0;
        for (int i = 0; i < 24; i++) g += (double)sstd[i];
        g /= 24.0;
        double asig  = 0.3 * (1.0 + g);
        double S1    = asig + 1e-6;
        double blend = 1.0 / (1.0 + exp(-(g - 0.1) * 10.0));
        double h  = 1.0 / 22.0;
        double d1 = h / S1;
        g_scal[0] = (float)S1;
        g_scal[1] = (float)(1.0 / S1);
        g_scal[2] = (float)blend;
        g_scal[3] = (float)exp(-d1 * d1);
        g_scal[4] = (float)cos(d1);
        g_scal[5] = (float)sin(d1);
        g_scal[6] = (float)d1;
        for (int b = 0; b < NB; b++) g_curvsum[b] = 0ull;
    }
}

// ============================================================
// Kernel 2: per-batch bitonic sort by x (u64 = flip(x)<<32 | idx)
// ============================================================
__global__ void __launch_bounds__(1024)
sort_kernel(const float* __restrict__ xyz) {
    __shared__ unsigned long long keys[NPTS];
    int b = blockIdx.x, tid = threadIdx.x;
    const float* base = xyz + (size_t)b * NPTS * 3;

    for (int e = tid; e < NPTS; e += 1024) {
        unsigned u = __float_as_uint(base[3 * e]);
        u ^= (u & 0x80000000u) ? 0xFFFFFFFFu : 0x80000000u;
        keys[e] = ((unsigned long long)u << 32) | (unsigned)e;
    }
    __syncthreads();

    for (int k = 2; k <= NPTS; k <<= 1) {
        for (int j = k >> 1; j > 0; j >>= 1) {
#pragma unroll
            for (int s = 0; s < 4; s++) {
                int e = tid + (s << 10);
                int p = e ^ j;
                if (p > e) {
                    unsigned long long a = keys[e], c = keys[p];
                    bool asc = ((e & k) == 0);
                    if ((a > c) == asc) { keys[e] = c; keys[p] = a; }
                }
            }
            __syncthreads();
        }
    }

    for (int e = tid; e < NPTS; e += 1024) {
        int idx = (int)(unsigned)(keys[e] & 0xFFFFFFFFu);
        float x = base[3 * idx], y = base[3 * idx + 1], z = base[3 * idx + 2];
        g_sorted[b * NPTS + e] = make_float4(x, y, z, __int_as_float(idx));
    }
}

// ============================================================
// Kernel 3: kNN via sorted-x window, branch-free float-only top-16,
// then threshold re-scan accumulating centered covariance sums.
// grid (32, NB), 128 threads, 64KB dyn smem, NO spills (<=256 regs)
// ============================================================
__global__ void __launch_bounds__(128, 2)
knn_kernel() {
    extern __shared__ float4 P[];   // 4096 * 16B = 64KB
    int b = blockIdx.y;
    for (int i = threadIdx.x; i < NPTS; i += 128) P[i] = g_sorted[b * NPTS + i];
    __syncthreads();

    int wi   = threadIdx.x >> 5, lane = threadIdx.x & 31;
    int wg   = wi * gridDim.x + blockIdx.x;     // strided warp->region map (balance)
    int sp   = wg * 32 + lane;
    float4 q = P[sp];

    // ---- phase 1: top-16 neighbor d^2 (floats only, unconditional insert) ----
    float L[16];
#pragma unroll
    for (int t = 0; t < 16; t++) L[t] = INF_F;

    int lo = sp, hi = sp;
    bool done = false;
    while (__any_sync(0xffffffffu, !done)) {
        float dLo = (lo > 0)        ? (q.x - P[lo - 1].x) : INF_F;
        float dHi = (hi < NPTS - 1) ? (P[hi + 1].x - q.x) : INF_F;
        bool  goLo = dLo <= dHi;
        float dmin = goLo ? dLo : dHi;
        done = done || (dmin * dmin > L[15]) || (dmin == INF_F);
        bool act = !done;
#pragma unroll
        for (int u = 1; u <= 8; u++) {
            int  j  = goLo ? (lo - u) : (hi + u);
            int  jc = j < 0 ? 0 : (j > NPTS - 1 ? NPTS - 1 : j);
            float4 c = P[jc];
            float dx = q.x - c.x, dy = q.y - c.y, dz = q.z - c.z;
            float d2 = fmaf(dz, dz, fmaf(dy, dy, dx * dx));
            bool valid = act && (j >= 0) && (j < NPTS);
            float v = valid ? d2 : INF_F;
            // sorted-insert via parallel min/max identity (depth-2, no branches)
            float pv = L[0];
            L[0] = fminf(v, L[0]);
#pragma unroll
            for (int t = 1; t < 16; t++) {
                float o = L[t];
                L[t] = fminf(fmaxf(v, pv), o);
                pv = o;
            }
        }
        if (act) { if (goLo) lo -= 8; else hi += 8; }
    }

    // ---- phase 2: rescan window extent, accumulate centered stats ----
    float tau = L[15];
    int loE = lo < 0 ? 0 : lo;
    int hiE = hi > NPTS - 1 ? NPTS - 1 : hi;

    float sx = 0.f, sy = 0.f, sz = 0.f;
    float sxx = 0.f, syy = 0.f, szz = 0.f, sxy = 0.f, sxz = 0.f, syz = 0.f;
#pragma unroll 4
    for (int j = loE; j <= hiE; j++) {
        float4 c = P[j];
        float dx = c.x - q.x, dy = c.y - q.y, dz = c.z - q.z;
        float d2 = fmaf(dz, dz, fmaf(dy, dy, dx * dx));
        float f  = ((d2 <= tau) && (j != sp)) ? 1.0f : 0.0f;
        dx *= f; dy *= f; dz *= f;
        sx += dx; sy += dy; sz += dz;
        sxx = fmaf(dx, dx, sxx); syy = fmaf(dy, dy, syy); szz = fmaf(dz, dz, szz);
        sxy = fmaf(dx, dy, sxy); sxz = fmaf(dx, dz, sxz); syz = fmaf(dy, dz, syz);
    }

    // cov of u = (neigh - q): cov = (S2 - 16*mu*mu')/15  (shift-invariant == ref)
    double mx = (double)sx / 16.0, my = (double)sy / 16.0, mz = (double)sz / 16.0;
    double cxx = ((double)sxx - 16.0 * mx * mx) / 15.0;
    double cyy = ((double)syy - 16.0 * my * my) / 15.0;
    double czz = ((double)szz - 16.0 * mz * mz) / 15.0;
    double cxy = ((double)sxy - 16.0 * mx * my) / 15.0;
    double cxz = ((double)sxz - 16.0 * mx * mz) / 15.0;
    double cyz = ((double)syz - 16.0 * my * mz) / 15.0;

    double tr = cxx + cyy + czz;
    double qm = tr / 3.0;
    double aa = cxx - qm, bb = cyy - qm, cc2 = czz - qm;
    double p2 = aa * aa + bb * bb + cc2 * cc2
              + 2.0 * (cxy * cxy + cxz * cxz + cyz * cyz);
    double lmin;
    if (p2 <= 1e-300) {
        lmin = qm;
    } else {
        double pp  = sqrt(p2 / 6.0);
        double inv = 1.0 / pp;
        double b00 = aa * inv, b11 = bb * inv, b22 = cc2 * inv;
        double b01 = cxy * inv, b02 = cxz * inv, b12 = cyz * inv;
        double det = b00 * (b11 * b22 - b12 * b12)
                   - b01 * (b01 * b22 - b12 * b02)
                   + b02 * (b01 * b12 - b11 * b02);
        double r = 0.5 * det;
        r = r < -1.0 ? -1.0 : (r > 1.0 ? 1.0 : r);
        double phi = acos(r) * (1.0 / 3.0);
        lmin = qm + 2.0 * pp * cos(phi + 2.0943951023931953);
    }

    double curv = lmin / (tr + 1e-6);
    int orig = __float_as_int(q.w);
    int gi   = b * NPTS + orig;
    g_curv[gi] = (float)curv;
    g_lstd[gi * 3 + 0] = (float)sqrt(cxx > 0.0 ? cxx : 0.0);
    g_lstd[gi * 3 + 1] = (float)sqrt(cyy > 0.0 ? cyy : 0.0);
    g_lstd[gi * 3 + 2] = (float)sqrt(czz > 0.0 ? czz : 0.0);

    long long sc = llrint(curv * 1099511627776.0);   // 2^40 fixed point (deterministic)
    atomicAdd(&g_curvsum[b], (unsigned long long)sc);
}

// ============================================================
// Kernel 4: embedding via geometric/rotation recurrences
// ============================================================
__global__ void __launch_bounds__(96)
embed_kernel(const float* __restrict__ xyz, float* __restrict__ out) {
    __shared__ float sm[32][129];
    int tid = threadIdx.x;
    int p = tid & 31;
    int d = tid >> 5;
    int b = blockIdx.y;
    int n0 = blockIdx.x * 32;
    int gp = b * NPTS + n0 + p;

    float x    = xyz[(size_t)gp * 3 + d];
    float lstd = g_lstd[(size_t)gp * 3 + d];
    float curv = g_curv[gp];
    float cm   = (float)((double)(long long)g_curvsum[b]
                         * (1.0 / 1099511627776.0) * (1.0 / 4096.0));
    float w    = 1.0f / (1.0f + __expf(-10.0f * (curv - cm)));

    float invS1 = g_scal[1], blend = g_scal[2];
    float Q1 = g_scal[3], cd1 = g_scal[4], sd1 = g_scal[5], d1 = g_scal[6];

    float Aw = w * blend;
    float Bw = w * (1.0f - blend);
    float Cw = 1.0f - w;

    const float h   = 0.045454545454545456f;   // 1/22
    const float fv0 = -0.9545454545454546f;    // FEAT_VAL[0]

    float S2   = fmaf(0.3f, lstd, 0.3f) + 1e-6f;
    float inv2 = 1.0f / S2;
    float d2s  = h * inv2;
    float Q2   = __expf(-d2s * d2s);

    bool  up  = (x <= 0.0f);
    float sgn = up ? 1.0f : -1.0f;
    int   f   = up ? 0 : 42;
    int   df  = up ? 1 : -1;
    float fva = up ? fv0 : -fv0;

    float t1 = (x - fva) * invS1;
    float t2 = (x - fva) * inv2;
    float G1 = __expf(-0.5f * t1 * t1);
    float G2 = __expf(-0.5f * t2 * t2);
    float r1 = __expf(sgn * d1  * (t1 - sgn * 0.5f * d1));
    float r2 = __expf(sgn * d2s * (t2 - sgn * 0.5f * d2s));
    float cc = __cosf(t1);
    float sn = __sinf(t1);
    float sd = up ? sd1 : -sd1;

    for (int it = 0; it < 43; it++) {
        float val = fmaf(Aw, G1, fmaf(Bw, cc, Cw * G2));
        int col;
        if (d < 2) col = d * 43 + f;
        else       col = (f < 41) ? (86 + f) : ((f == 42) ? 127 : -1);
        if (col >= 0) sm[p][col] = val;
        G1 *= r1; r1 *= Q1;
        G2 *= r2; r2 *= Q2;
        float cn  = fmaf(cc, cd1,  sn * sd);
        float sn2 = fmaf(sn, cd1, -cc * sd);
        cc = cn; sn = sn2;
        f += df;
    }
    __syncthreads();

    float* ob = out + ((size_t)b * NPTS + n0) * 128;
    for (int i = tid; i < 32 * 128; i += 96)
        ob[i] = sm[i >> 7][i & 127];
}

// ============================================================
extern "C" void kernel_launch(void* const* d_in, const int* in_sizes, int n_in,
                              void* d_out, int out_size) {
    const float* xyz = (const float*)d_in[0];
    float* out = (float*)d_out;
    (void)in_sizes; (void)n_in; (void)out_size;

    const int knn_smem = NPTS * 16;   // 65536 B
    cudaFuncSetAttribute(knn_kernel, cudaFuncAttributeMaxDynamicSharedMemorySize, knn_smem);

    pre_kernel<<<1, 768>>>(xyz);
    sort_kernel<<<NB, 1024>>>(xyz);
    dim3 kg(32, NB);
    knn_kernel<<<kg, 128, knn_smem>>>();
    dim3 eg(NPTS / 32, NB);
    embed_kernel<<<eg, 96>>>(xyz, out);
}

// round 12
// speedup vs baseline: 1.1339x; 1.0351x over previous
#include <cuda_runtime.h>
#include <math.h>

#define NB    8
#define NPTS  4096
#define PAD   16                     // sentinel entries each side
#define NTOT  (NPTS + 2 * PAD)       // 4128
#define BT    128                    // knn block threads
#define RING  112                    // shortlist capacity per thread
#define INF_F __int_as_float(0x7f800000)

// ---- scratch (device globals; no allocations allowed) ----
__device__ float  g_std24[24];
__device__ float  g_scal[8];                 // S1,1/S1,blend,Q1,cos(d1),sin(d1),d1
__device__ float  g_lstd[NB * NPTS * 3];
__device__ float  g_curv[NB * NPTS];
__device__ unsigned long long g_curvsum[NB]; // fixed-point (2^40) curvature sums
__device__ float4 g_sorted[NB * NPTS];       // per batch: sorted by x; .w = orig idx bits

// ============================================================
// Kernel 1: per-(batch,dim) std over N (ddof=1), 24 blocks
// ============================================================
__global__ void bd_std_kernel(const float* __restrict__ xyz) {
    __shared__ double ssum[256];
    __shared__ double ssq[256];
    int bd = blockIdx.x;
    const float* p = xyz + (bd / 3) * NPTS * 3 + (bd % 3);
    double s = 0.0, s2 = 0.0;
#pragma unroll
    for (int k = 0; k < NPTS / 256; k++) {
        double v = (double)p[3 * (threadIdx.x + k * 256)];
        s += v; s2 += v * v;
    }
    ssum[threadIdx.x] = s; ssq[threadIdx.x] = s2;
    __syncthreads();
    for (int off = 128; off > 0; off >>= 1) {
        if (threadIdx.x < off) {
            ssum[threadIdx.x] += ssum[threadIdx.x + off];
            ssq[threadIdx.x]  += ssq[threadIdx.x + off];
        }
        __syncthreads();
    }
    if (threadIdx.x == 0) {
        double mean = ssum[0] / NPTS;
        double var  = (ssq[0] - (double)NPTS * mean * mean) / (NPTS - 1);
        g_std24[bd] = (float)sqrt(var > 0.0 ? var : 0.0);
    }
}

// ============================================================
// Kernel 2: global scalars + zero curvsum
// ============================================================
__global__ void consts_kernel() {
    if (threadIdx.x != 0) return;
    double g = 0.0;
    for (int i = 0; i < 24; i++) g += (double)g_std24[i];
    g /= 24.0;
    double asig  = 0.3 * (1.0 + g);
    double S1    = asig + 1e-6;
    double blend = 1.0 / (1.0 + exp(-(g - 0.1) * 10.0));
    double h  = 1.0 / 22.0;
    double d1 = h / S1;
    g_scal[0] = (float)S1;
    g_scal[1] = (float)(1.0 / S1);
    g_scal[2] = (float)blend;
    g_scal[3] = (float)exp(-d1 * d1);
    g_scal[4] = (float)cos(d1);
    g_scal[5] = (float)sin(d1);
    g_scal[6] = (float)d1;
    for (int b = 0; b < NB; b++) g_curvsum[b] = 0ull;
}

// ============================================================
// Kernel 3: per-batch bitonic sort by x (u64 = flip(x)<<32 | idx)
// ============================================================
__global__ void __launch_bounds__(1024)
sort_kernel(const float* __restrict__ xyz) {
    __shared__ unsigned long long keys[NPTS];
    int b = blockIdx.x, tid = threadIdx.x;
    const float* base = xyz + (size_t)b * NPTS * 3;

    for (int e = tid; e < NPTS; e += 1024) {
        unsigned u = __float_as_uint(base[3 * e]);
        u ^= (u & 0x80000000u) ? 0xFFFFFFFFu : 0x80000000u;
        keys[e] = ((unsigned long long)u << 32) | (unsigned)e;
    }
    __syncthreads();

    for (int k = 2; k <= NPTS; k <<= 1) {
        for (int j = k >> 1; j > 0; j >>= 1) {
#pragma unroll
            for (int s = 0; s < 4; s++) {
                int e = tid + (s << 10);
                int p = e ^ j;
                if (p > e) {
                    unsigned long long a = keys[e], c = keys[p];
                    bool asc = ((e & k) == 0);
                    if ((a > c) == asc) { keys[e] = c; keys[p] = a; }
                }
            }
            __syncthreads();
        }
    }

    for (int e = tid; e < NPTS; e += 1024) {
        int idx = (int)(unsigned)(keys[e] & 0xFFFFFFFFu);
        float x = base[3 * idx], y = base[3 * idx + 1], z = base[3 * idx + 2];
        g_sorted[b * NPTS + e] = make_float4(x, y, z, __int_as_float(idx));
    }
}

// ============================================================
// Kernel 4: kNN via sorted-x window. EXACT f32 d2 top-16 (min/max
// network, vote-gated) + smem shortlist ring -> tiny phase-2.
// grid (32, NB), 128 threads, ~94.7KB dyn smem, 2 blocks/SM
// ============================================================
__global__ void __launch_bounds__(BT, 2)
knn_kernel() {
    extern __shared__ char smraw[];
    float4* P = (float4*)smraw;                                   // NTOT*16B
    unsigned short* ring = (unsigned short*)(smraw + NTOT * 16);  // RING*BT*2B

    int b = blockIdx.y;
    int tid = threadIdx.x;
    for (int i = tid; i < NPTS; i += BT) P[PAD + i] = g_sorted[b * NPTS + i];
    if (tid < 2 * PAD) {
        int at = (tid < PAD) ? tid : (NPTS + PAD + (tid - PAD));
        float sx = (tid < PAD) ? -3e18f : 3e18f;
        P[at] = make_float4(sx, 0.f, 0.f, 0.f);
    }
    __syncthreads();

    int wi   = tid >> 5, lane = tid & 31;
    int wg   = wi * gridDim.x + blockIdx.x;     // strided warp->region map (balance)
    int spj  = wg * 32 + lane + PAD;            // padded sorted position
    float4 q = P[spj];

    float L[16];
#pragma unroll
    for (int t = 0; t < 16; t++) L[t] = INF_F;

    int lo = spj, hi = spj;
    int cnt = 0;
    bool done = false;

    while (__any_sync(0xffffffffu, !done)) {
        float gLo = q.x - P[lo - 1].x;
        float gHi = P[hi + 1].x - q.x;
        bool  goLo = gLo <= gHi;
        float g    = goLo ? gLo : gHi;
        done = done || (g * g > L[15]);
        bool act = !done;
        int base = goLo ? lo : hi;
        int dir  = goLo ? -1 : 1;

        float d2a[8]; int ja[8];
        float vmin = INF_F;
#pragma unroll
        for (int u = 1; u <= 8; u++) {
            int j = base + dir * u;             // in-bounds via sentinels (PAD=16)
            float4 c = P[j];
            float dx = q.x - c.x, dy = q.y - c.y, dz = q.z - c.z;
            float d2 = fmaf(dz, dz, fmaf(dy, dy, dx * dx));
            float v = act ? d2 : INF_F;
            d2a[u - 1] = v; ja[u - 1] = j;
            vmin = fminf(vmin, v);
        }

        float L15pre = L[15];
        if (__any_sync(0xffffffffu, vmin < L15pre)) {
#pragma unroll
            for (int u = 0; u < 8; u++) {
                float v = d2a[u];
                // shortlist append (superset of final 16; exact filter later)
                if (v < L15pre) {
                    if (cnt < RING) ring[cnt * BT + tid] = (unsigned short)ja[u];
                    cnt++;
                }
                // exact sorted-insert via parallel min/max identity
                float pv = L[0];
                L[0] = fminf(v, L[0]);
#pragma unroll
                for (int t = 1; t < 16; t++) {
                    float o = L[t];
                    L[t] = fminf(fmaxf(v, pv), o);
                    pv = o;
                }
            }
        }
        if (act) { if (goLo) lo -= 8; else hi += 8; }
    }

    // ---- phase 2: accumulate centered stats over shortlist (exact tau filter) ----
    float tau = L[15];
    float sx = 0.f, sy = 0.f, sz = 0.f;
    float sxx = 0.f, syy = 0.f, szz = 0.f, sxy = 0.f, sxz = 0.f, syz = 0.f;

    bool ovf = (cnt > RING);
    if (!__any_sync(0xffffffffu, ovf)) {
        for (int i = 0; i < cnt; i++) {
            int j = ring[i * BT + tid];
            float4 c = P[j];
            float dx = c.x - q.x, dy = c.y - q.y, dz = c.z - q.z;
            float d2 = fmaf(dz, dz, fmaf(dy, dy, dx * dx));
            float f  = (d2 <= tau) ? 1.0f : 0.0f;
            dx *= f; dy *= f; dz *= f;
            sx += dx; sy += dy; sz += dz;
            sxx = fmaf(dx, dx, sxx); syy = fmaf(dy, dy, syy); szz = fmaf(dz, dz, szz);
            sxy = fmaf(dx, dy, sxy); sxz = fmaf(dx, dz, sxz); syz = fmaf(dy, dz, syz);
        }
    } else {
        // rare fallback: full-window rescan (covers ring overflow lanes too)
        for (int j = lo; j <= hi; j++) {
            float4 c = P[j];
            float dx = c.x - q.x, dy = c.y - q.y, dz = c.z - q.z;
            float d2 = fmaf(dz, dz, fmaf(dy, dy, dx * dx));
            float f  = ((d2 <= tau) && (j != spj)) ? 1.0f : 0.0f;
            dx *= f; dy *= f; dz *= f;
            sx += dx; sy += dy; sz += dz;
            sxx = fmaf(dx, dx, sxx); syy = fmaf(dy, dy, syy); szz = fmaf(dz, dz, szz);
            sxy = fmaf(dx, dy, sxy); sxz = fmaf(dx, dz, sxz); syz = fmaf(dy, dz, syz);
        }
    }

    // cov of u = (neigh - q): cov = (S2 - 16*mu*mu')/15  (shift-invariant == ref)
    double mx = (double)sx / 16.0, my = (double)sy / 16.0, mz = (double)sz / 16.0;
    double cxx = ((double)sxx - 16.0 * mx * mx) / 15.0;
    double cyy = ((double)syy - 16.0 * my * my) / 15.0;
    double czz = ((double)szz - 16.0 * mz * mz) / 15.0;
    double cxy = ((double)sxy - 16.0 * mx * my) / 15.0;
    double cxz = ((double)sxz - 16.0 * mx * mz) / 15.0;
    double cyz = ((double)syz - 16.0 * my * mz) / 15.0;

    double tr = cxx + cyy + czz;
    double qm = tr / 3.0;
    double aa = cxx - qm, bb = cyy - qm, cc2 = czz - qm;
    double p2 = aa * aa + bb * bb + cc2 * cc2
              + 2.0 * (cxy * cxy + cxz * cxz + cyz * cyz);
    double lmin;
    if (p2 <= 1e-300) {
        lmin = qm;
    } else {
        double pp  = sqrt(p2 / 6.0);
        double inv = 1.0 / pp;
        double b00 = aa * inv, b11 = bb * inv, b22 = cc2 * inv;
        double b01 = cxy * inv, b02 = cxz * inv, b12 = cyz * inv;
        double det = b00 * (b11 * b22 - b12 * b12)
                   - b01 * (b01 * b22 - b12 * b02)
                   + b02 * (b01 * b12 - b11 * b02);
        double r = 0.5 * det;
        r = r < -1.0 ? -1.0 : (r > 1.0 ? 1.0 : r);
        double phi = acos(r) * (1.0 / 3.0);
        lmin = qm + 2.0 * pp * cos(phi + 2.0943951023931953);
    }

    double curv = lmin / (tr + 1e-6);
    int orig = __float_as_int(q.w);
    int gi   = b * NPTS + orig;
    g_curv[gi] = (float)curv;
    g_lstd[gi * 3 + 0] = (float)sqrt(cxx > 0.0 ? cxx : 0.0);
    g_lstd[gi * 3 + 1] = (float)sqrt(cyy > 0.0 ? cyy : 0.0);
    g_lstd[gi * 3 + 2] = (float)sqrt(czz > 0.0 ? czz : 0.0);

    long long sc = llrint(curv * 1099511627776.0);   // 2^40 fixed point (deterministic)
    atomicAdd(&g_curvsum[b], (unsigned long long)sc);
}

// ============================================================
// Kernel 5: embedding via geometric/rotation recurrences
// ============================================================
__global__ void __launch_bounds__(96)
embed_kernel(const float* __restrict__ xyz, float* __restrict__ out) {
    __shared__ float sm[32][129];
    int tid = threadIdx.x;
    int p = tid & 31;
    int d = tid >> 5;
    int b = blockIdx.y;
    int n0 = blockIdx.x * 32;
    int gp = b * NPTS + n0 + p;

    float x    = xyz[(size_t)gp * 3 + d];
    float lstd = g_lstd[(size_t)gp * 3 + d];
    float curv = g_curv[gp];
    float cm   = (float)((double)(long long)g_curvsum[b]
                         * (1.0 / 1099511627776.0) * (1.0 / 4096.0));
    float w    = 1.0f / (1.0f + __expf(-10.0f * (curv - cm)));

    float invS1 = g_scal[1], blend = g_scal[2];
    float Q1 = g_scal[3], cd1 = g_scal[4], sd1 = g_scal[5], d1 = g_scal[6];

    float Aw = w * blend;
    float Bw = w * (1.0f - blend);
    float Cw = 1.0f - w;

    const float h   = 0.045454545454545456f;   // 1/22
    const float fv0 = -0.9545454545454546f;    // FEAT_VAL[0]

    float S2   = fmaf(0.3f, lstd, 0.3f) + 1e-6f;
    float inv2 = 1.0f / S2;
    float d2s  = h * inv2;
    float Q2   = __expf(-d2s * d2s);

    bool  up  = (x <= 0.0f);
    float sgn = up ? 1.0f : -1.0f;
    int   f   = up ? 0 : 42;
    int   df  = up ? 1 : -1;
    float fva = up ? fv0 : -fv0;

    float t1 = (x - fva) * invS1;
    float t2 = (x - fva) * inv2;
    float G1 = __expf(-0.5f * t1 * t1);
    float G2 = __expf(-0.5f * t2 * t2);
    float r1 = __expf(sgn * d1  * (t1 - sgn * 0.5f * d1));
    float r2 = __expf(sgn * d2s * (t2 - sgn * 0.5f * d2s));
    float cc = __cosf(t1);
    float sn = __sinf(t1);
    float sd = up ? sd1 : -sd1;

    for (int it = 0; it < 43; it++) {
        float val = fmaf(Aw, G1, fmaf(Bw, cc, Cw * G2));
        int col;
        if (d < 2) col = d * 43 + f;
        else       col = (f < 41) ? (86 + f) : ((f == 42) ? 127 : -1);
        if (col >= 0) sm[p][col] = val;
        G1 *= r1; r1 *= Q1;
        G2 *= r2; r2 *= Q2;
        float cn  = fmaf(cc, cd1,  sn * sd);
        float sn2 = fmaf(sn, cd1, -cc * sd);
        cc = cn; sn = sn2;
        f += df;
    }
    __syncthreads();

    float* ob = out + ((size_t)b * NPTS + n0) * 128;
    for (int i = tid; i < 32 * 128; i += 96)
        ob[i] = sm[i >> 7][i & 127];
}

// ============================================================
extern "C" void kernel_launch(void* const* d_in, const int* in_sizes, int n_in,
                              void* d_out, int out_size) {
    const float* xyz = (const float*)d_in[0];
    float* out = (float*)d_out;
    (void)in_sizes; (void)n_in; (void)out_size;

    const int knn_smem = NTOT * 16 + RING * BT * 2;   // 66048 + 28672 = 94720 B
    cudaFuncSetAttribute(knn_kernel, cudaFuncAttributeMaxDynamicSharedMemorySize, knn_smem);

    bd_std_kernel<<<24, 256>>>(xyz);
    consts_kernel<<<1, 32>>>();
    sort_kernel<<<NB, 1024>>>(xyz);
    dim3 kg(32, NB);
    knn_kernel<<<kg, BT, knn_smem>>>();
    dim3 eg(NPTS / 32, NB);
    embed_kernel<<<eg, 96>>>(xyz, out);
}

// round 13
// speedup vs baseline: 1.6095x; 1.4195x over previous
#include <cuda_runtime.h>
#include <math.h>

#define NB    8
#define NPTS  4096
#define PAD   16                     // sentinel entries each side
#define NTOT  (NPTS + 2 * PAD)       // 4128
#define BT    256                    // knn block threads (8 warps, 128 points)
#define INF_F __int_as_float(0x7f800000)

// ---- scratch (device globals; no allocations allowed) ----
__device__ float  g_std24[24];
__device__ float  g_scal[8];                 // S1,1/S1,blend,Q1,cos(d1),sin(d1),d1
__device__ float  g_lstd[NB * NPTS * 3];
__device__ float  g_curv[NB * NPTS];
__device__ unsigned long long g_curvsum[NB]; // fixed-point (2^40) curvature sums
__device__ float4 g_sorted[NB * NPTS];       // per batch: sorted by x; .w = orig idx bits

// ============================================================
// Kernel 1: per-(batch,dim) std over N (ddof=1), 24 blocks
// ============================================================
__global__ void bd_std_kernel(const float* __restrict__ xyz) {
    __shared__ double ssum[256];
    __shared__ double ssq[256];
    int bd = blockIdx.x;
    const float* p = xyz + (bd / 3) * NPTS * 3 + (bd % 3);
    double s = 0.0, s2 = 0.0;
#pragma unroll
    for (int k = 0; k < NPTS / 256; k++) {
        double v = (double)p[3 * (threadIdx.x + k * 256)];
        s += v; s2 += v * v;
    }
    ssum[threadIdx.x] = s; ssq[threadIdx.x] = s2;
    __syncthreads();
    for (int off = 128; off > 0; off >>= 1) {
        if (threadIdx.x < off) {
            ssum[threadIdx.x] += ssum[threadIdx.x + off];
            ssq[threadIdx.x]  += ssq[threadIdx.x + off];
        }
        __syncthreads();
    }
    if (threadIdx.x == 0) {
        double mean = ssum[0] / NPTS;
        double var  = (ssq[0] - (double)NPTS * mean * mean) / (NPTS - 1);
        g_std24[bd] = (float)sqrt(var > 0.0 ? var : 0.0);
    }
}

// ============================================================
// Kernel 2: global scalars + zero curvsum
// ============================================================
__global__ void consts_kernel() {
    if (threadIdx.x != 0) return;
    double g = 0.0;
    for (int i = 0; i < 24; i++) g += (double)g_std24[i];
    g /= 24.0;
    double asig  = 0.3 * (1.0 + g);
    double S1    = asig + 1e-6;
    double blend = 1.0 / (1.0 + exp(-(g - 0.1) * 10.0));
    double h  = 1.0 / 22.0;
    double d1 = h / S1;
    g_scal[0] = (float)S1;
    g_scal[1] = (float)(1.0 / S1);
    g_scal[2] = (float)blend;
    g_scal[3] = (float)exp(-d1 * d1);
    g_scal[4] = (float)cos(d1);
    g_scal[5] = (float)sin(d1);
    g_scal[6] = (float)d1;
    for (int b = 0; b < NB; b++) g_curvsum[b] = 0ull;
}

// ============================================================
// Kernel 3: per-batch bitonic sort by x (u64 = flip(x)<<32 | idx)
// ============================================================
__global__ void __launch_bounds__(1024)
sort_kernel(const float* __restrict__ xyz) {
    __shared__ unsigned long long keys[NPTS];
    int b = blockIdx.x, tid = threadIdx.x;
    const float* base = xyz + (size_t)b * NPTS * 3;

    for (int e = tid; e < NPTS; e += 1024) {
        unsigned u = __float_as_uint(base[3 * e]);
        u ^= (u & 0x80000000u) ? 0xFFFFFFFFu : 0x80000000u;
        keys[e] = ((unsigned long long)u << 32) | (unsigned)e;
    }
    __syncthreads();

    for (int k = 2; k <= NPTS; k <<= 1) {
        for (int j = k >> 1; j > 0; j >>= 1) {
#pragma unroll
            for (int s = 0; s < 4; s++) {
                int e = tid + (s << 10);
                int p = e ^ j;
                if (p > e) {
                    unsigned long long a = keys[e], c = keys[p];
                    bool asc = ((e & k) == 0);
                    if ((a > c) == asc) { keys[e] = c; keys[p] = a; }
                }
            }
            __syncthreads();
        }
    }

    for (int e = tid; e < NPTS; e += 1024) {
        int idx = (int)(unsigned)(keys[e] & 0xFFFFFFFFu);
        float x = base[3 * idx], y = base[3 * idx + 1], z = base[3 * idx + 2];
        g_sorted[b * NPTS + e] = make_float4(x, y, z, __int_as_float(idx));
    }
}

// ============================================================
// Kernel 4: pair-split kNN. Lane p / p+16 scan low/high side of the
// same point with fixed direction; thresholds exchanged via shfl;
// exact union top-16 via bitonic-merge identity; per-side rescan.
// grid (32, NB), 256 threads, 66KB smem, 3 blocks/SM.
// ============================================================
__global__ void __launch_bounds__(BT, 3)
knn_kernel() {
    extern __shared__ float4 P[];   // NTOT * 16B = 66048
    int b = blockIdx.y;
    int tid = threadIdx.x;
    for (int i = tid; i < NPTS; i += BT) P[PAD + i] = g_sorted[b * NPTS + i];
    if (tid < 2 * PAD) {
        int at = (tid < PAD) ? tid : (NPTS + PAD + (tid - PAD));
        float sx = (tid < PAD) ? -3e18f : 3e18f;
        P[at] = make_float4(sx, 0.f, 0.f, 0.f);
    }
    __syncthreads();

    int wi   = tid >> 5, lane = tid & 31;
    int pt   = lane & 15;                       // point within warp
    int side = lane >> 4;                       // 0 = low, 1 = high
    int dir  = side ? 1 : -1;
    int wg   = wi * gridDim.x + blockIdx.x;     // strided region map (balance)
    int spj  = wg * 16 + pt + PAD;
    float4 q = P[spj];

    float L[16];
#pragma unroll
    for (int t = 0; t < 16; t++) L[t] = INF_F;

    int   j0 = spj;
    float nx = P[spj + dir].x;                  // x of next candidate (prefetched)
    bool  done = false;

    while (__any_sync(0xffffffffu, !done)) {
        float pl15 = __shfl_xor_sync(0xffffffffu, L[15], 16);
        float thr  = fminf(fminf(L[15], pl15), 1e30f);   // 1e30: sentinel guard
        float g    = nx - q.x;
        done = done || (g * g > thr);
        bool act = !done;

        float d2a[8];
        float vmin = INF_F;
#pragma unroll
        for (int u = 1; u <= 8; u++) {
            float4 c = P[j0 + dir * u];
            float dx = q.x - c.x, dy = q.y - c.y, dz = q.z - c.z;
            float d2 = fmaf(dz, dz, fmaf(dy, dy, dx * dx));
            float v  = act ? d2 : INF_F;
            d2a[u - 1] = v;
            vmin = fminf(vmin, v);
        }
        float nx2 = P[j0 + dir * 9].x;          // prefetch next iteration's gap x

        if (vmin < L[15]) {                     // per-lane gate (SIMT-masked)
#pragma unroll
            for (int u = 0; u < 8; u++) {
                float v  = d2a[u];
                float pv = L[0];
                L[0] = fminf(v, L[0]);
#pragma unroll
                for (int t = 1; t < 16; t++) {
                    float o = L[t];
                    L[t] = fminf(fmaxf(v, pv), o);
                    pv = o;
                }
            }
        }
        if (act) { j0 += dir * 8; nx = nx2; }
    }

    // ---- exact union top-16 threshold: tau = max_i min(A[i], B[15-i]) ----
    __syncwarp();
    float tau = 0.0f;
#pragma unroll
    for (int i = 0; i < 16; i++) {
        float m = fminf(L[i], __shfl_xor_sync(0xffffffffu, L[15 - i], 16));
        tau = fmaxf(tau, m);
    }

    // ---- phase 2: per-side rescan (|dx| monotone -> early break) ----
    float sx = 0.f, sy = 0.f, sz = 0.f;
    float sxx = 0.f, syy = 0.f, szz = 0.f, sxy = 0.f, sxz = 0.f, syz = 0.f;
    for (int j = spj + dir; ; j += dir) {
        float4 c = P[j];
        float dx = c.x - q.x;
        if (dx * dx > tau) break;               // sentinel x guarantees exit
        float dy = c.y - q.y, dz = c.z - q.z;
        float d2 = fmaf(dz, dz, fmaf(dy, dy, dx * dx));
        float f  = (d2 <= tau) ? 1.0f : 0.0f;
        dx *= f; dy *= f; dz *= f;
        sx += dx; sy += dy; sz += dz;
        sxx = fmaf(dx, dx, sxx); syy = fmaf(dy, dy, syy); szz = fmaf(dz, dz, szz);
        sxy = fmaf(dx, dy, sxy); sxz = fmaf(dx, dz, sxz); syz = fmaf(dy, dz, syz);
    }
    __syncwarp();
    sx  += __shfl_xor_sync(0xffffffffu, sx,  16);
    sy  += __shfl_xor_sync(0xffffffffu, sy,  16);
    sz  += __shfl_xor_sync(0xffffffffu, sz,  16);
    sxx += __shfl_xor_sync(0xffffffffu, sxx, 16);
    syy += __shfl_xor_sync(0xffffffffu, syy, 16);
    szz += __shfl_xor_sync(0xffffffffu, szz, 16);
    sxy += __shfl_xor_sync(0xffffffffu, sxy, 16);
    sxz += __shfl_xor_sync(0xffffffffu, sxz, 16);
    syz += __shfl_xor_sync(0xffffffffu, syz, 16);

    long long sc = 0;
    if (side == 0) {
        // cov of u = (neigh - q): cov = (S2 - 16*mu*mu')/15 (shift-invariant == ref)
        double mx = (double)sx / 16.0, my = (double)sy / 16.0, mz = (double)sz / 16.0;
        double cxx = ((double)sxx - 16.0 * mx * mx) / 15.0;
        double cyy = ((double)syy - 16.0 * my * my) / 15.0;
        double czz = ((double)szz - 16.0 * mz * mz) / 15.0;
        double cxy = ((double)sxy - 16.0 * mx * my) / 15.0;
        double cxz = ((double)sxz - 16.0 * mx * mz) / 15.0;
        double cyz = ((double)syz - 16.0 * my * mz) / 15.0;

        double tr = cxx + cyy + czz;
        double qm = tr / 3.0;
        double aa = cxx - qm, bb = cyy - qm, cc2 = czz - qm;
        double p2 = aa * aa + bb * bb + cc2 * cc2
                  + 2.0 * (cxy * cxy + cxz * cxz + cyz * cyz);
        double lmin;
        if (p2 <= 1e-300) {
            lmin = qm;
        } else {
            double pp  = sqrt(p2 / 6.0);
            double inv = 1.0 / pp;
            double b00 = aa * inv, b11 = bb * inv, b22 = cc2 * inv;
            double b01 = cxy * inv, b02 = cxz * inv, b12 = cyz * inv;
            double det = b00 * (b11 * b22 - b12 * b12)
                       - b01 * (b01 * b22 - b12 * b02)
                       + b02 * (b01 * b12 - b11 * b02);
            double r = 0.5 * det;
            r = r < -1.0 ? -1.0 : (r > 1.0 ? 1.0 : r);
            double phi = acos(r) * (1.0 / 3.0);
            lmin = qm + 2.0 * pp * cos(phi + 2.0943951023931953);
        }

        double curv = lmin / (tr + 1e-6);
        int orig = __float_as_int(q.w);
        int gi   = b * NPTS + orig;
        g_curv[gi] = (float)curv;
        g_lstd[gi * 3 + 0] = (float)sqrt(cxx > 0.0 ? cxx : 0.0);
        g_lstd[gi * 3 + 1] = (float)sqrt(cyy > 0.0 ? cyy : 0.0);
        g_lstd[gi * 3 + 2] = (float)sqrt(czz > 0.0 ? czz : 0.0);

        sc = llrint(curv * 1099511627776.0);    // 2^40 fixed point (deterministic)
    }
    // warp-aggregated curvature sum (all lanes same batch)
    __syncwarp();
    unsigned long long usc = (unsigned long long)sc;
#pragma unroll
    for (int o = 16; o; o >>= 1)
        usc += __shfl_xor_sync(0xffffffffu, usc, o);
    if (lane == 0) atomicAdd(&g_curvsum[b], usc);
}

// ============================================================
// Kernel 5: embedding via geometric/rotation recurrences
// ============================================================
__global__ void __launch_bounds__(96)
embed_kernel(const float* __restrict__ xyz, float* __restrict__ out) {
    __shared__ float sm[32][129];
    int tid = threadIdx.x;
    int p = tid & 31;
    int d = tid >> 5;
    int b = blockIdx.y;
    int n0 = blockIdx.x * 32;
    int gp = b * NPTS + n0 + p;

    float x    = xyz[(size_t)gp * 3 + d];
    float lstd = g_lstd[(size_t)gp * 3 + d];
    float curv = g_curv[gp];
    float cm   = (float)((double)(long long)g_curvsum[b]
                         * (1.0 / 1099511627776.0) * (1.0 / 4096.0));
    float w    = 1.0f / (1.0f + __expf(-10.0f * (curv - cm)));

    float invS1 = g_scal[1], blend = g_scal[2];
    float Q1 = g_scal[3], cd1 = g_scal[4], sd1 = g_scal[5], d1 = g_scal[6];

    float Aw = w * blend;
    float Bw = w * (1.0f - blend);
    float Cw = 1.0f - w;

    const float h   = 0.045454545454545456f;   // 1/22
    const float fv0 = -0.9545454545454546f;    // FEAT_VAL[0]

    float S2   = fmaf(0.3f, lstd, 0.3f) + 1e-6f;
    float inv2 = 1.0f / S2;
    float d2s  = h * inv2;
    float Q2   = __expf(-d2s * d2s);

    bool  up  = (x <= 0.0f);
    float sgn = up ? 1.0f : -1.0f;
    int   f   = up ? 0 : 42;
    int   df  = up ? 1 : -1;
    float fva = up ? fv0 : -fv0;

    float t1 = (x - fva) * invS1;
    float t2 = (x - fva) * inv2;
    float G1 = __expf(-0.5f * t1 * t1);
    float G2 = __expf(-0.5f * t2 * t2);
    float r1 = __expf(sgn * d1  * (t1 - sgn * 0.5f * d1));
    float r2 = __expf(sgn * d2s * (t2 - sgn * 0.5f * d2s));
    float cc = __cosf(t1);
    float sn = __sinf(t1);
    float sd = up ? sd1 : -sd1;

    for (int it = 0; it < 43; it++) {
        float val = fmaf(Aw, G1, fmaf(Bw, cc, Cw * G2));
        int col;
        if (d < 2) col = d * 43 + f;
        else       col = (f < 41) ? (86 + f) : ((f == 42) ? 127 : -1);
        if (col >= 0) sm[p][col] = val;
        G1 *= r1; r1 *= Q1;
        G2 *= r2; r2 *= Q2;
        float cn  = fmaf(cc, cd1,  sn * sd);
        float sn2 = fmaf(sn, cd1, -cc * sd);
        cc = cn; sn = sn2;
        f += df;
    }
    __syncthreads();

    float* ob = out + ((size_t)b * NPTS + n0) * 128;
    for (int i = tid; i < 32 * 128; i += 96)
        ob[i] = sm[i >> 7][i & 127];
}

// ============================================================
extern "C" void kernel_launch(void* const* d_in, const int* in_sizes, int n_in,
                              void* d_out, int out_size) {
    const float* xyz = (const float*)d_in[0];
    float* out = (float*)d_out;
    (void)in_sizes; (void)n_in; (void)out_size;

    const int knn_smem = NTOT * 16;   // 66048 B
    cudaFuncSetAttribute(knn_kernel, cudaFuncAttributeMaxDynamicSharedMemorySize, knn_smem);

    bd_std_kernel<<<24, 256>>>(xyz);
    consts_kernel<<<1, 32>>>();
    sort_kernel<<<NB, 1024>>>(xyz);
    dim3 kg(NPTS / 128, NB);          // 32 x 8 = 256 blocks, fully resident
    knn_kernel<<<kg, BT, knn_smem>>>();
    dim3 eg(NPTS / 32, NB);
    embed_kernel<<<eg, 96>>>(xyz, out);
}

// round 15
// speedup vs baseline: 1.8335x; 1.1392x over previous
#include <cuda_runtime.h>
#include <math.h>

#define NB    8
#define NPTS  4096
#define PAD   32                     // sentinel entries each side (covers frozen-lane reach 32)
#define NTOT  (NPTS + 2 * PAD)       // 4160
#define BT    256                    // knn block threads: 8 warps = 64 points
#define INF_F __int_as_float(0x7f800000)

// ---- scratch (device globals; no allocations allowed) ----
__device__ float  g_std24[24];
__device__ float  g_scal[8];                 // S1,1/S1,blend,Q1,cos(d1),sin(d1),d1
__device__ float  g_lstd[NB * NPTS * 3];
__device__ float  g_curv[NB * NPTS];
__device__ unsigned long long g_curvsum[NB]; // fixed-point (2^40) curvature sums
__device__ float4 g_sorted[NB * NPTS];       // per batch: sorted by x; .w = orig idx bits

// ============================================================
// Kernel 1: per-(batch,dim) std over N (ddof=1), 24 blocks
// ============================================================
__global__ void bd_std_kernel(const float* __restrict__ xyz) {
    __shared__ double ssum[256];
    __shared__ double ssq[256];
    int bd = blockIdx.x;
    const float* p = xyz + (bd / 3) * NPTS * 3 + (bd % 3);
    double s = 0.0, s2 = 0.0;
#pragma unroll
    for (int k = 0; k < NPTS / 256; k++) {
        double v = (double)p[3 * (threadIdx.x + k * 256)];
        s += v; s2 += v * v;
    }
    ssum[threadIdx.x] = s; ssq[threadIdx.x] = s2;
    __syncthreads();
    for (int off = 128; off > 0; off >>= 1) {
        if (threadIdx.x < off) {
            ssum[threadIdx.x] += ssum[threadIdx.x + off];
            ssq[threadIdx.x]  += ssq[threadIdx.x + off];
        }
        __syncthreads();
    }
    if (threadIdx.x == 0) {
        double mean = ssum[0] / NPTS;
        double var  = (ssq[0] - (double)NPTS * mean * mean) / (NPTS - 1);
        g_std24[bd] = (float)sqrt(var > 0.0 ? var : 0.0);
    }
}

// ============================================================
// Kernel 2: global scalars + zero curvsum
// ============================================================
__global__ void consts_kernel() {
    if (threadIdx.x != 0) return;
    double g = 0.0;
    for (int i = 0; i < 24; i++) g += (double)g_std24[i];
    g /= 24.0;
    double asig  = 0.3 * (1.0 + g);
    double S1    = asig + 1e-6;
    double blend = 1.0 / (1.0 + exp(-(g - 0.1) * 10.0));
    double h  = 1.0 / 22.0;
    double d1 = h / S1;
    g_scal[0] = (float)S1;
    g_scal[1] = (float)(1.0 / S1);
    g_scal[2] = (float)blend;
    g_scal[3] = (float)exp(-d1 * d1);
    g_scal[4] = (float)cos(d1);
    g_scal[5] = (float)sin(d1);
    g_scal[6] = (float)d1;
    for (int b = 0; b < NB; b++) g_curvsum[b] = 0ull;
}

// ============================================================
// Kernel 3: per-batch bitonic sort by x (u64 = flip(x)<<32 | idx)
// ============================================================
__global__ void __launch_bounds__(1024)
sort_kernel(const float* __restrict__ xyz) {
    __shared__ unsigned long long keys[NPTS];
    int b = blockIdx.x, tid = threadIdx.x;
    const float* base = xyz + (size_t)b * NPTS * 3;

    for (int e = tid; e < NPTS; e += 1024) {
        unsigned u = __float_as_uint(base[3 * e]);
        u ^= (u & 0x80000000u) ? 0xFFFFFFFFu : 0x80000000u;
        keys[e] = ((unsigned long long)u << 32) | (unsigned)e;
    }
    __syncthreads();

    for (int k = 2; k <= NPTS; k <<= 1) {
        for (int j = k >> 1; j > 0; j >>= 1) {
#pragma unroll
            for (int s = 0; s < 4; s++) {
                int e = tid + (s << 10);
                int p = e ^ j;
                if (p > e) {
                    unsigned long long a = keys[e], c = keys[p];
                    bool asc = ((e & k) == 0);
                    if ((a > c) == asc) { keys[e] = c; keys[p] = a; }
                }
            }
            __syncthreads();
        }
    }

    for (int e = tid; e < NPTS; e += 1024) {
        int idx = (int)(unsigned)(keys[e] & 0xFFFFFFFFu);
        float x = base[3 * idx], y = base[3 * idx + 1], z = base[3 * idx + 2];
        g_sorted[b * NPTS + e] = make_float4(x, y, z, __int_as_float(idx));
    }
}

// ============================================================
// Kernel 4: 4-way-split kNN. Each point owned by 4 lanes:
// (side: low/high) x (parity: even/odd stride-2). 8 points/warp,
// contiguous mapping (correlated windows). Exact f32 top-16 per lane,
// per-candidate gated insert; union via bitonic merge + threshold id.
// grid (64, NB) = 512 blocks, 256 thr, ~66.5KB smem, 3 blocks/SM.
// Frozen-lane reads reach at most 32 past the points -> PAD=32.
// ============================================================
__global__ void __launch_bounds__(BT, 3)
knn_kernel() {
    extern __shared__ float4 P[];   // NTOT * 16B
    int b = blockIdx.y;
    int tid = threadIdx.x;
    for (int i = tid; i < NPTS; i += BT) P[PAD + i] = g_sorted[b * NPTS + i];
    if (tid < 2 * PAD) {
        int at = (tid < PAD) ? tid : (NPTS + PAD + (tid - PAD));
        float sx0 = (tid < PAD) ? -3e18f : 3e18f;
        P[at] = make_float4(sx0, 0.f, 0.f, 0.f);
    }
    __syncthreads();

    int wi   = tid >> 5, lane = tid & 31;
    int pt   = lane & 7;                        // point within warp (adjacent!)
    int sub  = lane >> 3;                       // 0..3
    int side = sub >> 1;                        // 0 = low, 1 = high
    int par  = sub & 1;                         // scan parity
    int dir  = side ? 1 : -1;
    int spj  = blockIdx.x * 64 + wi * 8 + pt + PAD;
    float4 q = P[spj];

    float L[16];
#pragma unroll
    for (int t = 0; t < 16; t++) L[t] = INF_F;

    int   jpos = spj + dir * (1 + par);
    float nx   = P[jpos].x;
    bool  done = false;

    while (__any_sync(0xffffffffu, !done)) {
        float t4 = fminf(L[15], __shfl_xor_sync(0xffffffffu, L[15], 8));
        t4 = fminf(t4, __shfl_xor_sync(0xffffffffu, t4, 16));
        float thr = fminf(t4, 1e30f);           // cap: sentinel gap (9e36) always stops
        float g   = side ? (nx - q.x) : (q.x - nx);
        done = done || (g * g > thr);
        bool act = !done;

        float nxn = P[jpos + dir * 16].x;       // prefetch next gap x (in-bounds: PAD=32)
#pragma unroll
        for (int u = 0; u < 8; u++) {
            float4 c = P[jpos + dir * 2 * u];
            float dx = q.x - c.x, dy = q.y - c.y, dz = q.z - c.z;
            float d2 = fmaf(dz, dz, fmaf(dy, dy, dx * dx));
            float v  = act ? d2 : INF_F;
            if (v < L[15]) {                    // per-candidate gate
                float pv = L[0];
                L[0] = fminf(v, L[0]);
#pragma unroll
                for (int t = 1; t < 16; t++) {
                    float o = L[t];
                    L[t] = fminf(fmaxf(v, pv), o);
                    pv = o;
                }
            }
        }
        if (act) { jpos += dir * 16; nx = nxn; }
    }

    // ---- union top-16 threshold over the 4 sub-lists (exact f32) ----
    __syncwarp();
    float E[16];
#pragma unroll
    for (int i = 0; i < 16; i++) {
        float bi = __shfl_xor_sync(0xffffffffu, L[15 - i], 8);
        E[i] = fminf(L[i], bi);                 // top-16 of pair union (bitonic seq)
    }
#pragma unroll
    for (int d = 8; d >= 1; d >>= 1) {          // bitonic clean -> ascending
#pragma unroll
        for (int i = 0; i < 16; i++) {
            if ((i & d) == 0) {
                float a2 = E[i], b2 = E[i + d];
                E[i] = fminf(a2, b2); E[i + d] = fmaxf(a2, b2);
            }
        }
    }
    float tau = 0.0f;
#pragma unroll
    for (int i = 0; i < 16; i++) {
        float m = fminf(E[i], __shfl_xor_sync(0xffffffffu, E[15 - i], 16));
        tau = fmaxf(tau, m);                    // 16th smallest of 4-way union
    }

    // ---- phase 2: per-lane stride-2 rescan, centered stats ----
    float sx = 0.f, sy = 0.f, sz = 0.f;
    float sxx = 0.f, syy = 0.f, szz = 0.f, sxy = 0.f, sxz = 0.f, syz = 0.f;
    for (int j = spj + dir * (1 + par); ; j += dir * 2) {
        float4 c = P[j];
        float dx = c.x - q.x;
        if (dx * dx > tau) break;               // sentinel x guarantees exit
        float dy = c.y - q.y, dz = c.z - q.z;
        float d2 = fmaf(dz, dz, fmaf(dy, dy, dx * dx));
        float f  = (d2 <= tau) ? 1.0f : 0.0f;
        dx *= f; dy *= f; dz *= f;
        sx += dx; sy += dy; sz += dz;
        sxx = fmaf(dx, dx, sxx); syy = fmaf(dy, dy, syy); szz = fmaf(dz, dz, szz);
        sxy = fmaf(dx, dy, sxy); sxz = fmaf(dx, dz, sxz); syz = fmaf(dy, dz, syz);
    }
    __syncwarp();
#pragma unroll
    for (int o = 8; o <= 16; o <<= 1) {
        sx  += __shfl_xor_sync(0xffffffffu, sx,  o);
        sy  += __shfl_xor_sync(0xffffffffu, sy,  o);
        sz  += __shfl_xor_sync(0xffffffffu, sz,  o);
        sxx += __shfl_xor_sync(0xffffffffu, sxx, o);
        syy += __shfl_xor_sync(0xffffffffu, syy, o);
        szz += __shfl_xor_sync(0xffffffffu, szz, o);
        sxy += __shfl_xor_sync(0xffffffffu, sxy, o);
        sxz += __shfl_xor_sync(0xffffffffu, sxz, o);
        syz += __shfl_xor_sync(0xffffffffu, syz, o);
    }

    long long sc = 0;
    if (sub == 0) {
        // cov of u = (neigh - q): cov = (S2 - 16*mu*mu')/15 (shift-invariant == ref)
        double mx = (double)sx / 16.0, my = (double)sy / 16.0, mz = (double)sz / 16.0;
        double cxx = ((double)sxx - 16.0 * mx * mx) / 15.0;
        double cyy = ((double)syy - 16.0 * my * my) / 15.0;
        double czz = ((double)szz - 16.0 * mz * mz) / 15.0;
        double cxy = ((double)sxy - 16.0 * mx * my) / 15.0;
        double cxz = ((double)sxz - 16.0 * mx * mz) / 15.0;
        double cyz = ((double)syz - 16.0 * my * mz) / 15.0;

        double tr = cxx + cyy + czz;
        double qm = tr / 3.0;
        double aa = cxx - qm, bb = cyy - qm, cc2 = czz - qm;
        double p2 = aa * aa + bb * bb + cc2 * cc2
                  + 2.0 * (cxy * cxy + cxz * cxz + cyz * cyz);
        double lmin;
        if (p2 <= 1e-300) {
            lmin = qm;
        } else {
            double pp  = sqrt(p2 / 6.0);
            double inv = 1.0 / pp;
            double b00 = aa * inv, b11 = bb * inv, b22 = cc2 * inv;
            double b01 = cxy * inv, b02 = cxz * inv, b12 = cyz * inv;
            double det = b00 * (b11 * b22 - b12 * b12)
                       - b01 * (b01 * b22 - b12 * b02)
                       + b02 * (b01 * b12 - b11 * b02);
            double r = 0.5 * det;
            r = r < -1.0 ? -1.0 : (r > 1.0 ? 1.0 : r);
            double phi = acos(r) * (1.0 / 3.0);
            lmin = qm + 2.0 * pp * cos(phi + 2.0943951023931953);
        }

        double curv = lmin / (tr + 1e-6);
        int orig = __float_as_int(q.w);
        int gi   = b * NPTS + orig;
        g_curv[gi] = (float)curv;
        g_lstd[gi * 3 + 0] = (float)sqrt(cxx > 0.0 ? cxx : 0.0);
        g_lstd[gi * 3 + 1] = (float)sqrt(cyy > 0.0 ? cyy : 0.0);
        g_lstd[gi * 3 + 2] = (float)sqrt(czz > 0.0 ? czz : 0.0);

        sc = llrint(curv * 1099511627776.0);    // 2^40 fixed point (deterministic)
    }
    __syncwarp();
    unsigned long long usc = (unsigned long long)sc;
#pragma unroll
    for (int o = 16; o; o >>= 1)
        usc += __shfl_xor_sync(0xffffffffu, usc, o);
    if (lane == 0) atomicAdd(&g_curvsum[b], usc);
}

// ============================================================
// Kernel 5: embedding via geometric/rotation recurrences
// ============================================================
__global__ void __launch_bounds__(96)
embed_kernel(const float* __restrict__ xyz, float* __restrict__ out) {
    __shared__ float sm[32][129];
    int tid = threadIdx.x;
    int p = tid & 31;
    int d = tid >> 5;
    int b = blockIdx.y;
    int n0 = blockIdx.x * 32;
    int gp = b * NPTS + n0 + p;

    float x    = xyz[(size_t)gp * 3 + d];
    float lstd = g_lstd[(size_t)gp * 3 + d];
    float curv = g_curv[gp];
    float cm   = (float)((double)(long long)g_curvsum[b]
                         * (1.0 / 1099511627776.0) * (1.0 / 4096.0));
    float w    = 1.0f / (1.0f + __expf(-10.0f * (curv - cm)));

    float invS1 = g_scal[1], blend = g_scal[2];
    float Q1 = g_scal[3], cd1 = g_scal[4], sd1 = g_scal[5], d1 = g_scal[6];

    float Aw = w * blend;
    float Bw = w * (1.0f - blend);
    float Cw = 1.0f - w;

    const float h   = 0.045454545454545456f;   // 1/22
    const float fv0 = -0.9545454545454546f;    // FEAT_VAL[0]

    float S2   = fmaf(0.3f, lstd, 0.3f) + 1e-6f;
    float inv2 = 1.0f / S2;
    float d2s  = h * inv2;
    float Q2   = __expf(-d2s * d2s);

    bool  up  = (x <= 0.0f);
    float sgn = up ? 1.0f : -1.0f;
    int   f   = up ? 0 : 42;
    int   df  = up ? 1 : -1;
    float fva = up ? fv0 : -fv0;

    float t1 = (x - fva) * invS1;
    float t2 = (x - fva) * inv2;
    float G1 = __expf(-0.5f * t1 * t1);
    float G2 = __expf(-0.5f * t2 * t2);
    float r1 = __expf(sgn * d1  * (t1 - sgn * 0.5f * d1));
    float r2 = __expf(sgn * d2s * (t2 - sgn * 0.5f * d2s));
    float cc = __cosf(t1);
    float sn = __sinf(t1);
    float sd = up ? sd1 : -sd1;

    for (int it = 0; it < 43; it++) {
        float val = fmaf(Aw, G1, fmaf(Bw, cc, Cw * G2));
        int col;
        if (d < 2) col = d * 43 + f;
        else       col = (f < 41) ? (86 + f) : ((f == 42) ? 127 : -1);
        if (col >= 0) sm[p][col] = val;
        G1 *= r1; r1 *= Q1;
        G2 *= r2; r2 *= Q2;
        float cn  = fmaf(cc, cd1,  sn * sd);
        float sn2 = fmaf(sn, cd1, -cc * sd);
        cc = cn; sn = sn2;
        f += df;
    }
    __syncthreads();

    float* ob = out + ((size_t)b * NPTS + n0) * 128;
    for (int i = tid; i < 32 * 128; i += 96)
        ob[i] = sm[i >> 7][i & 127];
}

// ============================================================
extern "C" void kernel_launch(void* const* d_in, const int* in_sizes, int n_in,
                              void* d_out, int out_size) {
    const float* xyz = (const float*)d_in[0];
    float* out = (float*)d_out;
    (void)in_sizes; (void)n_in; (void)out_size;

    const int knn_smem = NTOT * 16;   // 66560 B
    cudaFuncSetAttribute(knn_kernel, cudaFuncAttributeMaxDynamicSharedMemorySize, knn_smem);

    bd_std_kernel<<<24, 256>>>(xyz);
    consts_kernel<<<1, 32>>>();
    sort_kernel<<<NB, 1024>>>(xyz);
    dim3 kg(NPTS / 64, NB);           // 64 x 8 = 512 blocks
    knn_kernel<<<kg, BT, knn_smem>>>();
    dim3 eg(NPTS / 32, NB);
    embed_kernel<<<eg, 96>>>(xyz, out);
}